// round 13
// baseline (speedup 1.0000x reference)
#include <cuda_runtime.h>
#include <cuda_fp16.h>

#define NMAX 50000
#define EMAX 800000

// ---- scratch (static device globals; allocation-free per harness rules) ----
__device__ float g_deg[NMAX];
__device__ float g_dinv[NMAX];
__device__ int   g_rowptr[NMAX + 1];
__device__ int   g_cursor[NMAX];
__device__ int   g_blocksums[64];
__device__ int   g_srcs[EMAX];
__device__ float g_norms[EMAX];
__device__ __align__(16) float g_bufA[(size_t)NMAX * 128];   // also used as half storage
__device__ __align__(16) float g_bufB[(size_t)NMAX * 128];

// ---------------------------------------------------------------------------
__global__ void k_init(int n) {
    int i = blockIdx.x * blockDim.x + threadIdx.x;
    if (i < n) { g_deg[i] = 1.0f; g_cursor[i] = 0; }  // self-loop weight 1
}

__global__ void k_edge_count(const int* __restrict__ src, const int* __restrict__ dst,
                             const float* __restrict__ ew, int e) {
    int i = blockIdx.x * blockDim.x + threadIdx.x;
    if (i < e) {
        int d = dst[i];
        atomicAdd(&g_deg[d], ew[i]);
        atomicAdd(&g_cursor[d], 1);
    }
}

// phase 1: per-block (1024) warp-shuffle scan of counts; fused dinv
__global__ void k_scan_block(int n) {
    __shared__ int wsum[32];
    int tid = threadIdx.x;
    int i = blockIdx.x * 1024 + tid;
    int v = (i < n) ? g_cursor[i] : 0;
    int x = v;
#pragma unroll
    for (int off = 1; off < 32; off <<= 1) {
        int t = __shfl_up_sync(0xffffffffu, x, off);
        if ((tid & 31) >= off) x += t;
    }
    if ((tid & 31) == 31) wsum[tid >> 5] = x;
    __syncthreads();
    if (tid < 32) {
        int s = wsum[tid];
#pragma unroll
        for (int off = 1; off < 32; off <<= 1) {
            int t = __shfl_up_sync(0xffffffffu, s, off);
            if (tid >= off) s += t;
        }
        wsum[tid] = s;
    }
    __syncthreads();
    int incl = x + ((tid >= 32) ? wsum[(tid >> 5) - 1] : 0);
    if (i < n) g_rowptr[i] = incl - v;          // block-local exclusive
    if (tid == 1023) g_blocksums[blockIdx.x] = incl;
    if (i < n) g_dinv[i] = rsqrtf(g_deg[i]);    // deg >= 1 (self-loop)
}

// phase 2: each block reduces its prefix of block sums itself, adds offset
__global__ void k_scan_add(int n, int e) {
    __shared__ int s_off;
    int tid = threadIdx.x;
    if (tid < 32) {
        int bid = blockIdx.x;
        int v = 0;
        if (tid < bid) v = g_blocksums[tid];
        if (tid + 32 < bid) v += g_blocksums[tid + 32];
#pragma unroll
        for (int o = 16; o; o >>= 1) v += __shfl_down_sync(0xffffffffu, v, o);
        if (tid == 0) s_off = v;
    }
    __syncthreads();
    int i = blockIdx.x * 1024 + tid;
    if (i < n) {
        int r = g_rowptr[i] + s_off;
        g_rowptr[i] = r;
        g_cursor[i] = r;
    }
    if (i == 0) g_rowptr[n] = e;
}

__global__ void k_scatter(const int* __restrict__ src, const int* __restrict__ dst,
                          const float* __restrict__ ew, int e) {
    int i = blockIdx.x * blockDim.x + threadIdx.x;
    if (i < e) {
        int d = dst[i];
        int s = src[i];
        int pos = atomicAdd(&g_cursor[d], 1);
        g_srcs[pos]  = s;
        g_norms[pos] = g_dinv[s] * ew[i] * g_dinv[d];
    }
}

// ---------------------------------------------------------------------------
// Tensor-core GEMM: C[M,NC] = A[M,128] @ W[128,NC] (+bias)(+relu)
// 2-term compensation: acc = Al*Bh + Ah*Bh  (full-precision A x hi-fp16 B).
// __launch_bounds__(256, 2): ~127 live regs now fits the 128 cap -> 2 CTAs/SM.
__device__ __forceinline__ void mma_f16(float* c, const unsigned* a, const unsigned* b) {
    asm volatile("mma.sync.aligned.m16n8k16.row.col.f32.f16.f16.f32 "
        "{%0,%1,%2,%3}, {%4,%5,%6,%7}, {%8,%9}, {%0,%1,%2,%3};"
        : "+f"(c[0]), "+f"(c[1]), "+f"(c[2]), "+f"(c[3])
        : "r"(a[0]), "r"(a[1]), "r"(a[2]), "r"(a[3]), "r"(b[0]), "r"(b[1]));
}

__device__ __forceinline__ void ldsm4(unsigned& r0, unsigned& r1, unsigned& r2, unsigned& r3,
                                      const void* p) {
    unsigned addr = (unsigned)__cvta_generic_to_shared(p);
    asm volatile("ldmatrix.sync.aligned.m8n8.x4.shared.b16 {%0,%1,%2,%3}, [%4];"
        : "=r"(r0), "=r"(r1), "=r"(r2), "=r"(r3) : "r"(addr));
}

__device__ __forceinline__ void ldsm4t(unsigned& r0, unsigned& r1, unsigned& r2, unsigned& r3,
                                       const void* p) {
    unsigned addr = (unsigned)__cvta_generic_to_shared(p);
    asm volatile("ldmatrix.sync.aligned.m8n8.x4.trans.shared.b16 {%0,%1,%2,%3}, [%4];"
        : "=r"(r0), "=r"(r1), "=r"(r2), "=r"(r3) : "r"(addr));
}

template <int NC, bool BIAS, bool RELU, bool OUT16>
__global__ void __launch_bounds__(256, 2) k_gemm_tc(const float* __restrict__ A,
                                                    const float* __restrict__ W,
                                                    const float* __restrict__ bias,
                                                    void* __restrict__ Cv, int M) {
    const int KC = 32, KP = 40;             // A rows padded: stride 80B, LDSM conflict-free
    const int NP = NC + 8;                  // B rows padded: stride (NC+8)*2B, conflict-free
    const int NF = NC / 16;                 // n-fragments per warp (warp tile N = NC/2)
    const int NH = NC / 2;                  // half2 per B row
    const int PB = (KC * NH) / 256;         // B half2 per thread per tile
    __shared__ __half As_h[128][KP], As_l[128][KP];
    __shared__ __half Bs_h[KC][NP];

    int tid  = threadIdx.x;
    int lane = tid & 31, wid = tid >> 5;
    int m0   = blockIdx.x * 128;
    int wm0  = (wid & 3) * 32;
    int wn0  = (wid >> 2) * (NC / 2);
    int gr = lane >> 2, gc = lane & 3;

    float acc[2][NF][4];
#pragma unroll
    for (int i = 0; i < 2; i++)
#pragma unroll
        for (int j = 0; j < NF; j++)
#pragma unroll
            for (int q = 0; q < 4; q++) acc[i][j][q] = 0.f;

    int r16 = tid >> 4;      // 0..15 row-within-pass for A fill
    int c2  = tid & 15;      // half2 column for A fill

    float2 pa[8];            // prefetched A (8 rows x 2 floats)
    float2 pb[PB];           // prefetched B

    // ldmatrix lane addressing (computed once)
    int atq = lane >> 3, arr = lane & 7;
    int am_off = (atq & 1) * 8 + arr;      // + wm0 + i*16
    int ak_off = (atq >> 1) * 8;           // + ks
    int bjj = lane >> 4, bt = (lane >> 3) & 1;
    int bk_off = bt * 8 + (lane & 7);      // + ks

    auto loadA = [&](int k0) {
#pragma unroll
        for (int p = 0; p < 8; p++) {
            int gm = m0 + p * 16 + r16;
            pa[p] = (gm < M) ? *(const float2*)(A + (size_t)gm * 128 + k0 + 2 * c2)
                             : make_float2(0.f, 0.f);
        }
    };
    auto loadB = [&](int k0) {
#pragma unroll
        for (int p = 0; p < PB; p++) {
            int idx = p * 256 + tid;
            int kk = idx / NH, cb = idx % NH;
            pb[p] = *(const float2*)(W + (k0 + kk) * NC + 2 * cb);
        }
    };

    loadA(0);
    loadB(0);

#pragma unroll
    for (int k0 = 0; k0 < 128; k0 += KC) {
        // A: split prefetched fp32 to (hi,lo) fp16; B: hi-only
#pragma unroll
        for (int p = 0; p < 8; p++) {
            int r = p * 16 + r16;
            float2 v = pa[p];
            __half hx = __float2half_rn(v.x), hy = __float2half_rn(v.y);
            __half lx = __float2half_rn(v.x - __half2float(hx));
            __half ly = __float2half_rn(v.y - __half2float(hy));
            *(__half2*)&As_h[r][2 * c2] = __halves2half2(hx, hy);
            *(__half2*)&As_l[r][2 * c2] = __halves2half2(lx, ly);
        }
#pragma unroll
        for (int p = 0; p < PB; p++) {
            int idx = p * 256 + tid;
            int kk = idx / NH, cb = idx % NH;
            *(__half2*)&Bs_h[kk][2 * cb] = __floats2half2_rn(pb[p].x, pb[p].y);
        }
        __syncthreads();
        // prefetch next tile (global latency overlaps mma below)
        if (k0 + KC < 128) { loadA(k0 + KC); loadB(k0 + KC); }

#pragma unroll
        for (int k16 = 0; k16 < KC / 16; k16++) {
            int ks = k16 * 16;
            unsigned Ah[2][4], Al[2][4];
#pragma unroll
            for (int i = 0; i < 2; i++) {
                int am = wm0 + i * 16 + am_off;
                ldsm4(Ah[i][0], Ah[i][1], Ah[i][2], Ah[i][3], &As_h[am][ks + ak_off]);
                ldsm4(Al[i][0], Al[i][1], Al[i][2], Al[i][3], &As_l[am][ks + ak_off]);
            }
            unsigned Bh[NF][2];
#pragma unroll
            for (int jb = 0; jb < NF; jb += 2) {
                int bn = wn0 + (jb + bjj) * 8;
                int bk = ks + bk_off;
                ldsm4t(Bh[jb][0], Bh[jb][1], Bh[jb + 1][0], Bh[jb + 1][1], &Bs_h[bk][bn]);
            }
#pragma unroll
            for (int i = 0; i < 2; i++)
#pragma unroll
                for (int j = 0; j < NF; j++) {
                    mma_f16(acc[i][j], Al[i], Bh[j]);   // small term first
                    mma_f16(acc[i][j], Ah[i], Bh[j]);
                }
        }
        __syncthreads();
    }

    // epilogue
#pragma unroll
    for (int i = 0; i < 2; i++) {
#pragma unroll
        for (int j = 0; j < NF; j++) {
            int col = wn0 + j * 8 + gc * 2;
            float b0 = 0.f, b1 = 0.f;
            if (BIAS) { b0 = bias[col]; b1 = bias[col + 1]; }
            int gm0 = m0 + wm0 + i * 16 + gr;
            float x0 = acc[i][j][0] + b0, x1 = acc[i][j][1] + b1;
            float x2 = acc[i][j][2] + b0, x3 = acc[i][j][3] + b1;
            if (RELU) {
                x0 = fmaxf(x0, 0.f); x1 = fmaxf(x1, 0.f);
                x2 = fmaxf(x2, 0.f); x3 = fmaxf(x3, 0.f);
            }
            if (OUT16) {
                __half* C = (__half*)Cv;
                if (gm0 < M)
                    *(__half2*)(C + (size_t)gm0 * NC + col) = __floats2half2_rn(x0, x1);
                if (gm0 + 8 < M)
                    *(__half2*)(C + (size_t)(gm0 + 8) * NC + col) = __floats2half2_rn(x2, x3);
            } else {
                float* C = (float*)Cv;
                if (gm0 < M)
                    *(float2*)(C + (size_t)gm0 * NC + col) = make_float2(x0, x1);
                if (gm0 + 8 < M)
                    *(float2*)(C + (size_t)(gm0 + 8) * NC + col) = make_float2(x2, x3);
            }
        }
    }
}

// ---------------------------------------------------------------------------
// out[i,:] = relu( sum_{p in CSR(i)} norm[p]*h16[src[p],:] + dinv[i]^2*h16[i,:] + bias )
// h in fp16 (halved gather bytes); fp32 accumulation; one warp per node, 4 dims/lane.
__global__ void __launch_bounds__(256) k_aggregate(const __half* __restrict__ h,
                                                   const float* __restrict__ bias,
                                                   float* __restrict__ out, int n) {
    int warp = (blockIdx.x * blockDim.x + threadIdx.x) >> 5;
    int lane = threadIdx.x & 31;
    if (warp >= n) return;

    float di = g_dinv[warp];
    float sl = di * di;

    uint2 sv = ((const uint2*)(h + (size_t)warp * 128))[lane];
    float2 f0 = __half22float2(*(__half2*)&sv.x);
    float2 f1 = __half22float2(*(__half2*)&sv.y);
    float4 acc = make_float4(f0.x * sl, f0.y * sl, f1.x * sl, f1.y * sl);

    int p  = g_rowptr[warp];
    int p1 = g_rowptr[warp + 1];
    for (; p + 1 < p1; p += 2) {
        int   s0 = g_srcs[p],  s1 = g_srcs[p + 1];
        float w0 = g_norms[p], w1 = g_norms[p + 1];
        uint2 v0 = ((const uint2*)(h + (size_t)s0 * 128))[lane];
        uint2 v1 = ((const uint2*)(h + (size_t)s1 * 128))[lane];
        float2 a0 = __half22float2(*(__half2*)&v0.x);
        float2 a1 = __half22float2(*(__half2*)&v0.y);
        float2 b0 = __half22float2(*(__half2*)&v1.x);
        float2 b1 = __half22float2(*(__half2*)&v1.y);
        acc.x += w0 * a0.x + w1 * b0.x;
        acc.y += w0 * a0.y + w1 * b0.y;
        acc.z += w0 * a1.x + w1 * b1.x;
        acc.w += w0 * a1.y + w1 * b1.y;
    }
    if (p < p1) {
        int   s0 = g_srcs[p];
        float w0 = g_norms[p];
        uint2 v0 = ((const uint2*)(h + (size_t)s0 * 128))[lane];
        float2 a0 = __half22float2(*(__half2*)&v0.x);
        float2 a1 = __half22float2(*(__half2*)&v0.y);
        acc.x += w0 * a0.x;
        acc.y += w0 * a0.y;
        acc.z += w0 * a1.x;
        acc.w += w0 * a1.y;
    }
    float4 b = ((const float4*)bias)[lane];
    acc.x = fmaxf(acc.x + b.x, 0.f);
    acc.y = fmaxf(acc.y + b.y, 0.f);
    acc.z = fmaxf(acc.z + b.z, 0.f);
    acc.w = fmaxf(acc.w + b.w, 0.f);
    ((float4*)(out + (size_t)warp * 128))[lane] = acc;
}

// ---------------------------------------------------------------------------
extern "C" void kernel_launch(void* const* d_in, const int* in_sizes, int n_in,
                              void* d_out, int out_size) {
    const float* x   = (const float*)d_in[0];
    const int*   ei  = (const int*)  d_in[1];
    const float* ew  = (const float*)d_in[2];
    const float* W1  = (const float*)d_in[3];
    const float* b1  = (const float*)d_in[4];
    const float* W2  = (const float*)d_in[5];
    const float* b2  = (const float*)d_in[6];
    const float* Wf1 = (const float*)d_in[7];
    const float* bf1 = (const float*)d_in[8];
    const float* Wf2 = (const float*)d_in[9];
    const float* bf2 = (const float*)d_in[10];
    float* out = (float*)d_out;

    int n = in_sizes[0] / 128;   // 50000
    int e = in_sizes[2];         // 800000
    const int* src = ei;
    const int* dst = ei + e;

    float *bufA = nullptr, *bufB = nullptr;
    cudaGetSymbolAddress((void**)&bufA, g_bufA);
    cudaGetSymbolAddress((void**)&bufB, g_bufB);
    __half* bufA16 = (__half*)bufA;

    const int TB = 256;
    int gn = (n + TB - 1) / TB;
    int ge = (e + TB - 1) / TB;
    int nb = (n + 1023) / 1024;

    // ---- graph preprocessing: degrees + CSR by dst
    k_init<<<gn, TB>>>(n);
    k_edge_count<<<ge, TB>>>(src, dst, ew, e);
    k_scan_block<<<nb, 1024>>>(n);
    k_scan_add<<<nb, 1024>>>(n, e);
    k_scatter<<<ge, TB>>>(src, dst, ew, e);

    int gm = (n + 127) / 128;
    int ga = (n * 32 + TB - 1) / TB;   // one warp per node

    // conv1: h16 = x @ W1 ; aggregate(+b1, relu) -> fp32
    k_gemm_tc<128, false, false, true ><<<gm, TB>>>(x, W1, nullptr, bufA16, n);
    k_aggregate<<<ga, TB>>>(bufA16, b1, bufB, n);
    // conv2
    k_gemm_tc<128, false, false, true ><<<gm, TB>>>(bufB, W2, nullptr, bufA16, n);
    k_aggregate<<<ga, TB>>>(bufA16, b2, bufB, n);
    // fc1 + relu (fp32 out)
    k_gemm_tc<128, true, true, false><<<gm, TB>>>(bufB, Wf1, bf1, bufA, n);
    // fc2 -> output
    k_gemm_tc<64, true, false, false><<<gm, TB>>>(bufA, Wf2, bf2, out, n);
}

// round 15
// speedup vs baseline: 1.0776x; 1.0776x over previous
#include <cuda_runtime.h>
#include <cuda_fp16.h>

#define NMAX 50000
#define EMAX 800000

// ---- scratch (static device globals; allocation-free per harness rules) ----
__device__ float g_deg[NMAX];
__device__ float g_dinv[NMAX];
__device__ int   g_rowptr[NMAX + 1];
__device__ int   g_cursor[NMAX];
__device__ int   g_blocksums[64];
__device__ int   g_srcs[EMAX];
__device__ float g_norms[EMAX];
__device__ __align__(16) float g_bufA[(size_t)NMAX * 128];   // also used as half storage
__device__ __align__(16) float g_bufB[(size_t)NMAX * 128];

// ---------------------------------------------------------------------------
__global__ void k_init(int n) {
    int i = blockIdx.x * blockDim.x + threadIdx.x;
    if (i < n) { g_deg[i] = 1.0f; g_cursor[i] = 0; }  // self-loop weight 1
}

__global__ void k_edge_count(const int* __restrict__ src, const int* __restrict__ dst,
                             const float* __restrict__ ew, int e) {
    int i = blockIdx.x * blockDim.x + threadIdx.x;
    if (i < e) {
        int d = dst[i];
        atomicAdd(&g_deg[d], ew[i]);
        atomicAdd(&g_cursor[d], 1);
    }
}

// phase 1: per-block (1024) warp-shuffle scan of counts; fused dinv
__global__ void k_scan_block(int n) {
    __shared__ int wsum[32];
    int tid = threadIdx.x;
    int i = blockIdx.x * 1024 + tid;
    int v = (i < n) ? g_cursor[i] : 0;
    int x = v;
#pragma unroll
    for (int off = 1; off < 32; off <<= 1) {
        int t = __shfl_up_sync(0xffffffffu, x, off);
        if ((tid & 31) >= off) x += t;
    }
    if ((tid & 31) == 31) wsum[tid >> 5] = x;
    __syncthreads();
    if (tid < 32) {
        int s = wsum[tid];
#pragma unroll
        for (int off = 1; off < 32; off <<= 1) {
            int t = __shfl_up_sync(0xffffffffu, s, off);
            if (tid >= off) s += t;
        }
        wsum[tid] = s;
    }
    __syncthreads();
    int incl = x + ((tid >= 32) ? wsum[(tid >> 5) - 1] : 0);
    if (i < n) g_rowptr[i] = incl - v;          // block-local exclusive
    if (tid == 1023) g_blocksums[blockIdx.x] = incl;
    if (i < n) g_dinv[i] = rsqrtf(g_deg[i]);    // deg >= 1 (self-loop)
}

// phase 2: each block reduces its prefix of block sums itself, adds offset
__global__ void k_scan_add(int n, int e) {
    __shared__ int s_off;
    int tid = threadIdx.x;
    if (tid < 32) {
        int bid = blockIdx.x;
        int v = 0;
        if (tid < bid) v = g_blocksums[tid];
        if (tid + 32 < bid) v += g_blocksums[tid + 32];
#pragma unroll
        for (int o = 16; o; o >>= 1) v += __shfl_down_sync(0xffffffffu, v, o);
        if (tid == 0) s_off = v;
    }
    __syncthreads();
    int i = blockIdx.x * 1024 + tid;
    if (i < n) {
        int r = g_rowptr[i] + s_off;
        g_rowptr[i] = r;
        g_cursor[i] = r;
    }
    if (i == 0) g_rowptr[n] = e;
}

__global__ void k_scatter(const int* __restrict__ src, const int* __restrict__ dst,
                          const float* __restrict__ ew, int e) {
    int i = blockIdx.x * blockDim.x + threadIdx.x;
    if (i < e) {
        int d = dst[i];
        int s = src[i];
        int pos = atomicAdd(&g_cursor[d], 1);
        g_srcs[pos]  = s;
        g_norms[pos] = g_dinv[s] * ew[i] * g_dinv[d];
    }
}

// ---------------------------------------------------------------------------
// mma / ldmatrix helpers
__device__ __forceinline__ void mma_f16(float* c, const unsigned* a, const unsigned* b) {
    asm volatile("mma.sync.aligned.m16n8k16.row.col.f32.f16.f16.f32 "
        "{%0,%1,%2,%3}, {%4,%5,%6,%7}, {%8,%9}, {%0,%1,%2,%3};"
        : "+f"(c[0]), "+f"(c[1]), "+f"(c[2]), "+f"(c[3])
        : "r"(a[0]), "r"(a[1]), "r"(a[2]), "r"(a[3]), "r"(b[0]), "r"(b[1]));
}

__device__ __forceinline__ void ldsm4(unsigned& r0, unsigned& r1, unsigned& r2, unsigned& r3,
                                      const void* p) {
    unsigned addr = (unsigned)__cvta_generic_to_shared(p);
    asm volatile("ldmatrix.sync.aligned.m8n8.x4.shared.b16 {%0,%1,%2,%3}, [%4];"
        : "=r"(r0), "=r"(r1), "=r"(r2), "=r"(r3) : "r"(addr));
}

__device__ __forceinline__ void ldsm4t(unsigned& r0, unsigned& r1, unsigned& r2, unsigned& r3,
                                       const void* p) {
    unsigned addr = (unsigned)__cvta_generic_to_shared(p);
    asm volatile("ldmatrix.sync.aligned.m8n8.x4.trans.shared.b16 {%0,%1,%2,%3}, [%4];"
        : "=r"(r0), "=r"(r1), "=r"(r2), "=r"(r3) : "r"(addr));
}

// ---------------------------------------------------------------------------
// Tensor-core GEMM (conv layers): C[M,128] = A[M,128] @ W[128,128]
// 2-term compensation: acc = Al*Bh + Ah*Bh; fp16 output for the aggregate.
template <int NC, bool OUT16>
__global__ void __launch_bounds__(256) k_gemm_tc(const float* __restrict__ A,
                                                 const float* __restrict__ W,
                                                 void* __restrict__ Cv, int M) {
    const int KC = 32, KP = 40;             // A rows padded: stride 80B, LDSM conflict-free
    const int NP = NC + 8;                  // B rows padded
    const int NF = NC / 16;
    const int NH = NC / 2;
    const int PB = (KC * NH) / 256;
    __shared__ __half As_h[128][KP], As_l[128][KP];
    __shared__ __half Bs_h[KC][NP];

    int tid  = threadIdx.x;
    int lane = tid & 31, wid = tid >> 5;
    int m0   = blockIdx.x * 128;
    int wm0  = (wid & 3) * 32;
    int wn0  = (wid >> 2) * (NC / 2);
    int gr = lane >> 2, gc = lane & 3;

    float acc[2][NF][4];
#pragma unroll
    for (int i = 0; i < 2; i++)
#pragma unroll
        for (int j = 0; j < NF; j++)
#pragma unroll
            for (int q = 0; q < 4; q++) acc[i][j][q] = 0.f;

    int r16 = tid >> 4;
    int c2  = tid & 15;

    float2 pa[8];
    float2 pb[PB];

    int atq = lane >> 3, arr = lane & 7;
    int am_off = (atq & 1) * 8 + arr;
    int ak_off = (atq >> 1) * 8;
    int bjj = lane >> 4, bt = (lane >> 3) & 1;
    int bk_off = bt * 8 + (lane & 7);

    auto loadA = [&](int k0) {
#pragma unroll
        for (int p = 0; p < 8; p++) {
            int gm = m0 + p * 16 + r16;
            pa[p] = (gm < M) ? *(const float2*)(A + (size_t)gm * 128 + k0 + 2 * c2)
                             : make_float2(0.f, 0.f);
        }
    };
    auto loadB = [&](int k0) {
#pragma unroll
        for (int p = 0; p < PB; p++) {
            int idx = p * 256 + tid;
            int kk = idx / NH, cb = idx % NH;
            pb[p] = *(const float2*)(W + (k0 + kk) * NC + 2 * cb);
        }
    };

    loadA(0);
    loadB(0);

#pragma unroll
    for (int k0 = 0; k0 < 128; k0 += KC) {
#pragma unroll
        for (int p = 0; p < 8; p++) {
            int r = p * 16 + r16;
            float2 v = pa[p];
            __half hx = __float2half_rn(v.x), hy = __float2half_rn(v.y);
            __half lx = __float2half_rn(v.x - __half2float(hx));
            __half ly = __float2half_rn(v.y - __half2float(hy));
            *(__half2*)&As_h[r][2 * c2] = __halves2half2(hx, hy);
            *(__half2*)&As_l[r][2 * c2] = __halves2half2(lx, ly);
        }
#pragma unroll
        for (int p = 0; p < PB; p++) {
            int idx = p * 256 + tid;
            int kk = idx / NH, cb = idx % NH;
            *(__half2*)&Bs_h[kk][2 * cb] = __floats2half2_rn(pb[p].x, pb[p].y);
        }
        __syncthreads();
        if (k0 + KC < 128) { loadA(k0 + KC); loadB(k0 + KC); }

#pragma unroll
        for (int k16 = 0; k16 < KC / 16; k16++) {
            int ks = k16 * 16;
            unsigned Ah[2][4], Al[2][4];
#pragma unroll
            for (int i = 0; i < 2; i++) {
                int am = wm0 + i * 16 + am_off;
                ldsm4(Ah[i][0], Ah[i][1], Ah[i][2], Ah[i][3], &As_h[am][ks + ak_off]);
                ldsm4(Al[i][0], Al[i][1], Al[i][2], Al[i][3], &As_l[am][ks + ak_off]);
            }
            unsigned Bh[NF][2];
#pragma unroll
            for (int jb = 0; jb < NF; jb += 2) {
                int bn = wn0 + (jb + bjj) * 8;
                int bk = ks + bk_off;
                ldsm4t(Bh[jb][0], Bh[jb][1], Bh[jb + 1][0], Bh[jb + 1][1], &Bs_h[bk][bn]);
            }
#pragma unroll
            for (int i = 0; i < 2; i++)
#pragma unroll
                for (int j = 0; j < NF; j++) {
                    mma_f16(acc[i][j], Al[i], Bh[j]);
                    mma_f16(acc[i][j], Ah[i], Bh[j]);
                }
        }
        __syncthreads();
    }

#pragma unroll
    for (int i = 0; i < 2; i++) {
#pragma unroll
        for (int j = 0; j < NF; j++) {
            int col = wn0 + j * 8 + gc * 2;
            int gm0 = m0 + wm0 + i * 16 + gr;
            if (OUT16) {
                __half* C = (__half*)Cv;
                if (gm0 < M)
                    *(__half2*)(C + (size_t)gm0 * NC + col) =
                        __floats2half2_rn(acc[i][j][0], acc[i][j][1]);
                if (gm0 + 8 < M)
                    *(__half2*)(C + (size_t)(gm0 + 8) * NC + col) =
                        __floats2half2_rn(acc[i][j][2], acc[i][j][3]);
            } else {
                float* C = (float*)Cv;
                if (gm0 < M)
                    *(float2*)(C + (size_t)gm0 * NC + col) = make_float2(acc[i][j][0], acc[i][j][1]);
                if (gm0 + 8 < M)
                    *(float2*)(C + (size_t)(gm0 + 8) * NC + col) = make_float2(acc[i][j][2], acc[i][j][3]);
            }
        }
    }
}

// ---------------------------------------------------------------------------
// Fused FC: out[M,64] = relu(A[M,128] @ Wf1 + bf1) @ Wf2 + bf2
// Phase 1 = 2-term GEMM; fc1 result kept in smem as fp16;
// Phase 2 = fc2 mma from smem (NF2=4 fragments: full 32-col warp tile).
#define SM_ASH 0
#define SM_ASL 10240
#define SM_BSH 20480          // 32 x 136 halves
#define SM_F   29184          // 128 x 136 halves (fc1 result, hi fp16)
#define SM_B2  64000          // 128 x 72 halves (Wf2)
#define SM_FUSED_TOTAL 82432

__global__ void __launch_bounds__(256) k_fc_fused(const float* __restrict__ A,
                                                  const float* __restrict__ W1,
                                                  const float* __restrict__ b1,
                                                  const float* __restrict__ W2,
                                                  const float* __restrict__ b2,
                                                  float* __restrict__ out, int M) {
    extern __shared__ char sm[];
    __half (*As_h)[40]  = (__half(*)[40])(sm + SM_ASH);
    __half (*As_l)[40]  = (__half(*)[40])(sm + SM_ASL);
    __half (*Bs_h)[136] = (__half(*)[136])(sm + SM_BSH);
    __half (*F)[136]    = (__half(*)[136])(sm + SM_F);
    __half (*B2)[72]    = (__half(*)[72])(sm + SM_B2);

    int tid  = threadIdx.x;
    int lane = tid & 31, wid = tid >> 5;
    int m0   = blockIdx.x * 128;
    int wm0  = (wid & 3) * 32;
    int wn0  = (wid >> 2) * 64;
    int gr = lane >> 2, gc = lane & 3;

    float acc[2][8][4];
#pragma unroll
    for (int i = 0; i < 2; i++)
#pragma unroll
        for (int j = 0; j < 8; j++)
#pragma unroll
            for (int q = 0; q < 4; q++) acc[i][j][q] = 0.f;

    int r16 = tid >> 4;
    int c2  = tid & 15;

    float2 pa[8];
    float2 pb[8];

    int atq = lane >> 3, arr = lane & 7;
    int am_off = (atq & 1) * 8 + arr;
    int ak_off = (atq >> 1) * 8;
    int bjj = lane >> 4, bt = (lane >> 3) & 1;
    int bk_off = bt * 8 + (lane & 7);

    auto loadA = [&](int k0) {
#pragma unroll
        for (int p = 0; p < 8; p++) {
            int gm = m0 + p * 16 + r16;
            pa[p] = (gm < M) ? *(const float2*)(A + (size_t)gm * 128 + k0 + 2 * c2)
                             : make_float2(0.f, 0.f);
        }
    };
    auto loadB = [&](int k0) {
#pragma unroll
        for (int p = 0; p < 8; p++) {
            int idx = p * 256 + tid;
            int kk = idx / 64, cb = idx % 64;
            pb[p] = *(const float2*)(W1 + (k0 + kk) * 128 + 2 * cb);
        }
    };

    loadA(0);
    loadB(0);

    // preload Wf2 [128,64] -> B2 (hi fp16, k-major); visible after next sync
#pragma unroll
    for (int p = 0; p < 32; p++) {
        int idx = p * 256 + tid;
        int kk = idx >> 6, nn = idx & 63;
        B2[kk][nn] = __float2half_rn(W2[idx]);
    }

    // ---- phase 1: fc1 (2-term) ----
#pragma unroll
    for (int k0 = 0; k0 < 128; k0 += 32) {
#pragma unroll
        for (int p = 0; p < 8; p++) {
            int r = p * 16 + r16;
            float2 v = pa[p];
            __half hx = __float2half_rn(v.x), hy = __float2half_rn(v.y);
            __half lx = __float2half_rn(v.x - __half2float(hx));
            __half ly = __float2half_rn(v.y - __half2float(hy));
            *(__half2*)&As_h[r][2 * c2] = __halves2half2(hx, hy);
            *(__half2*)&As_l[r][2 * c2] = __halves2half2(lx, ly);
        }
#pragma unroll
        for (int p = 0; p < 8; p++) {
            int idx = p * 256 + tid;
            int kk = idx / 64, cb = idx % 64;
            *(__half2*)&Bs_h[kk][2 * cb] = __floats2half2_rn(pb[p].x, pb[p].y);
        }
        __syncthreads();
        if (k0 + 32 < 128) { loadA(k0 + 32); loadB(k0 + 32); }

#pragma unroll
        for (int k16 = 0; k16 < 2; k16++) {
            int ks = k16 * 16;
            unsigned Ah[2][4], Al[2][4];
#pragma unroll
            for (int i = 0; i < 2; i++) {
                int am = wm0 + i * 16 + am_off;
                ldsm4(Ah[i][0], Ah[i][1], Ah[i][2], Ah[i][3], &As_h[am][ks + ak_off]);
                ldsm4(Al[i][0], Al[i][1], Al[i][2], Al[i][3], &As_l[am][ks + ak_off]);
            }
            unsigned Bh[8][2];
#pragma unroll
            for (int jb = 0; jb < 8; jb += 2) {
                int bn = wn0 + (jb + bjj) * 8;
                int bk = ks + bk_off;
                ldsm4t(Bh[jb][0], Bh[jb][1], Bh[jb + 1][0], Bh[jb + 1][1], &Bs_h[bk][bn]);
            }
#pragma unroll
            for (int i = 0; i < 2; i++)
#pragma unroll
                for (int j = 0; j < 8; j++) {
                    mma_f16(acc[i][j], Al[i], Bh[j]);
                    mma_f16(acc[i][j], Ah[i], Bh[j]);
                }
        }
        __syncthreads();
    }

    // epilogue 1: bias + relu -> F (fp16, smem), local rows
#pragma unroll
    for (int i = 0; i < 2; i++) {
#pragma unroll
        for (int j = 0; j < 8; j++) {
            int col = wn0 + j * 8 + gc * 2;
            float b0 = b1[col], bb1 = b1[col + 1];
            int r0 = wm0 + i * 16 + gr;
            float x0 = fmaxf(acc[i][j][0] + b0, 0.f), x1 = fmaxf(acc[i][j][1] + bb1, 0.f);
            float x2 = fmaxf(acc[i][j][2] + b0, 0.f), x3 = fmaxf(acc[i][j][3] + bb1, 0.f);
            *(__half2*)&F[r0][col]     = __floats2half2_rn(x0, x1);
            *(__half2*)&F[r0 + 8][col] = __floats2half2_rn(x2, x3);
        }
    }
    __syncthreads();

    // ---- phase 2: fc2 (N=64), A = F (hi fp16), B = B2; warp tile 32 cols ----
    int wn2 = (wid >> 2) * 32;
    float acc2[2][4][4];
#pragma unroll
    for (int i = 0; i < 2; i++)
#pragma unroll
        for (int j = 0; j < 4; j++)
#pragma unroll
            for (int q = 0; q < 4; q++) acc2[i][j][q] = 0.f;

#pragma unroll
    for (int k16 = 0; k16 < 8; k16++) {
        int ks = k16 * 16;
        unsigned Ah2[2][4];
#pragma unroll
        for (int i = 0; i < 2; i++) {
            int am = wm0 + i * 16 + am_off;
            ldsm4(Ah2[i][0], Ah2[i][1], Ah2[i][2], Ah2[i][3], &F[am][ks + ak_off]);
        }
        unsigned Bh2[4][2];
#pragma unroll
        for (int jb = 0; jb < 4; jb += 2) {
            int bn = wn2 + (jb + bjj) * 8;
            int bk = ks + bk_off;
            ldsm4t(Bh2[jb][0], Bh2[jb][1], Bh2[jb + 1][0], Bh2[jb + 1][1], &B2[bk][bn]);
        }
#pragma unroll
        for (int i = 0; i < 2; i++)
#pragma unroll
            for (int j = 0; j < 4; j++)
                mma_f16(acc2[i][j], Ah2[i], Bh2[j]);
    }

    // epilogue 2: bias -> fp32 out [M,64]
#pragma unroll
    for (int i = 0; i < 2; i++) {
#pragma unroll
        for (int j = 0; j < 4; j++) {
            int col = wn2 + j * 8 + gc * 2;
            float b0 = b2[col], bb1 = b2[col + 1];
            int gm0 = m0 + wm0 + i * 16 + gr;
            if (gm0 < M)
                *(float2*)(out + (size_t)gm0 * 64 + col) =
                    make_float2(acc2[i][j][0] + b0, acc2[i][j][1] + bb1);
            if (gm0 + 8 < M)
                *(float2*)(out + (size_t)(gm0 + 8) * 64 + col) =
                    make_float2(acc2[i][j][2] + b0, acc2[i][j][3] + bb1);
        }
    }
}

// ---------------------------------------------------------------------------
// out[i,:] = relu( sum_{p in CSR(i)} norm[p]*h16[src[p],:] + dinv[i]^2*h16[i,:] + bias )
__global__ void __launch_bounds__(256) k_aggregate(const __half* __restrict__ h,
                                                   const float* __restrict__ bias,
                                                   float* __restrict__ out, int n) {
    int warp = (blockIdx.x * blockDim.x + threadIdx.x) >> 5;
    int lane = threadIdx.x & 31;
    if (warp >= n) return;

    float di = g_dinv[warp];
    float sl = di * di;

    uint2 sv = ((const uint2*)(h + (size_t)warp * 128))[lane];
    float2 f0 = __half22float2(*(__half2*)&sv.x);
    float2 f1 = __half22float2(*(__half2*)&sv.y);
    float4 acc = make_float4(f0.x * sl, f0.y * sl, f1.x * sl, f1.y * sl);

    int p  = g_rowptr[warp];
    int p1 = g_rowptr[warp + 1];
    for (; p + 1 < p1; p += 2) {
        int   s0 = g_srcs[p],  s1 = g_srcs[p + 1];
        float w0 = g_norms[p], w1 = g_norms[p + 1];
        uint2 v0 = ((const uint2*)(h + (size_t)s0 * 128))[lane];
        uint2 v1 = ((const uint2*)(h + (size_t)s1 * 128))[lane];
        float2 a0 = __half22float2(*(__half2*)&v0.x);
        float2 a1 = __half22float2(*(__half2*)&v0.y);
        float2 b0 = __half22float2(*(__half2*)&v1.x);
        float2 b1 = __half22float2(*(__half2*)&v1.y);
        acc.x += w0 * a0.x + w1 * b0.x;
        acc.y += w0 * a0.y + w1 * b0.y;
        acc.z += w0 * a1.x + w1 * b1.x;
        acc.w += w0 * a1.y + w1 * b1.y;
    }
    if (p < p1) {
        int   s0 = g_srcs[p];
        float w0 = g_norms[p];
        uint2 v0 = ((const uint2*)(h + (size_t)s0 * 128))[lane];
        float2 a0 = __half22float2(*(__half2*)&v0.x);
        float2 a1 = __half22float2(*(__half2*)&v0.y);
        acc.x += w0 * a0.x;
        acc.y += w0 * a0.y;
        acc.z += w0 * a1.x;
        acc.w += w0 * a1.y;
    }
    float4 b = ((const float4*)bias)[lane];
    acc.x = fmaxf(acc.x + b.x, 0.f);
    acc.y = fmaxf(acc.y + b.y, 0.f);
    acc.z = fmaxf(acc.z + b.z, 0.f);
    acc.w = fmaxf(acc.w + b.w, 0.f);
    ((float4*)(out + (size_t)warp * 128))[lane] = acc;
}

// ---------------------------------------------------------------------------
extern "C" void kernel_launch(void* const* d_in, const int* in_sizes, int n_in,
                              void* d_out, int out_size) {
    const float* x   = (const float*)d_in[0];
    const int*   ei  = (const int*)  d_in[1];
    const float* ew  = (const float*)d_in[2];
    const float* W1  = (const float*)d_in[3];
    const float* b1  = (const float*)d_in[4];
    const float* W2  = (const float*)d_in[5];
    const float* b2  = (const float*)d_in[6];
    const float* Wf1 = (const float*)d_in[7];
    const float* bf1 = (const float*)d_in[8];
    const float* Wf2 = (const float*)d_in[9];
    const float* bf2 = (const float*)d_in[10];
    float* out = (float*)d_out;

    int n = in_sizes[0] / 128;   // 50000
    int e = in_sizes[2];         // 800000
    const int* src = ei;
    const int* dst = ei + e;

    float *bufA = nullptr, *bufB = nullptr;
    cudaGetSymbolAddress((void**)&bufA, g_bufA);
    cudaGetSymbolAddress((void**)&bufB, g_bufB);
    __half* bufA16 = (__half*)bufA;

    static int smem_set = 0;
    if (!smem_set) {
        cudaFuncSetAttribute(k_fc_fused, cudaFuncAttributeMaxDynamicSharedMemorySize,
                             SM_FUSED_TOTAL);
        smem_set = 1;
    }

    const int TB = 256;
    int gn = (n + TB - 1) / TB;
    int ge = (e + TB - 1) / TB;
    int nb = (n + 1023) / 1024;

    // ---- graph preprocessing: degrees + CSR by dst
    k_init<<<gn, TB>>>(n);
    k_edge_count<<<ge, TB>>>(src, dst, ew, e);
    k_scan_block<<<nb, 1024>>>(n);
    k_scan_add<<<nb, 1024>>>(n, e);
    k_scatter<<<ge, TB>>>(src, dst, ew, e);

    int gm = (n + 127) / 128;
    int ga = (n * 32 + TB - 1) / TB;   // one warp per node

    // conv1: h16 = x @ W1 ; aggregate(+b1, relu) -> fp32
    k_gemm_tc<128, true><<<gm, TB>>>(x, W1, bufA16, n);
    k_aggregate<<<ga, TB>>>(bufA16, b1, bufB, n);
    // conv2
    k_gemm_tc<128, true><<<gm, TB>>>(bufB, W2, bufA16, n);
    k_aggregate<<<ga, TB>>>(bufA16, b2, bufB, n);
    // fused fc1+fc2 -> fp32 output
    k_fc_fused<<<gm, TB, SM_FUSED_TOTAL>>>(bufB, Wf1, bf1, Wf2, bf2, out, n);
}

// round 16
// speedup vs baseline: 1.1332x; 1.0517x over previous
#include <cuda_runtime.h>
#include <cuda_fp16.h>

#define NMAX 50000
#define EMAX 800000

// ---- scratch (static device globals; allocation-free per harness rules) ----
__device__ float g_deg[NMAX];
__device__ float g_dinv[NMAX];
__device__ int   g_rowptr[NMAX + 1];
__device__ int   g_cursor[NMAX];
__device__ int   g_blocksums[64];
__device__ int   g_srcs[EMAX];
__device__ float g_norms[EMAX];
__device__ __align__(16) float g_bufA[(size_t)NMAX * 128];   // also used as half storage
__device__ __align__(16) float g_bufB[(size_t)NMAX * 128];

// ---------------------------------------------------------------------------
__global__ void k_init(int n) {
    int i = blockIdx.x * blockDim.x + threadIdx.x;
    if (i < n) { g_deg[i] = 1.0f; g_cursor[i] = 0; }  // self-loop weight 1
}

__global__ void k_edge_count(const int* __restrict__ src, const int* __restrict__ dst,
                             const float* __restrict__ ew, int e) {
    int i = blockIdx.x * blockDim.x + threadIdx.x;
    if (i < e) {
        int d = dst[i];
        atomicAdd(&g_deg[d], ew[i]);
        atomicAdd(&g_cursor[d], 1);
    }
}

// phase 1: per-block (1024) warp-shuffle scan of counts; fused dinv
__global__ void k_scan_block(int n) {
    __shared__ int wsum[32];
    int tid = threadIdx.x;
    int i = blockIdx.x * 1024 + tid;
    int v = (i < n) ? g_cursor[i] : 0;
    int x = v;
#pragma unroll
    for (int off = 1; off < 32; off <<= 1) {
        int t = __shfl_up_sync(0xffffffffu, x, off);
        if ((tid & 31) >= off) x += t;
    }
    if ((tid & 31) == 31) wsum[tid >> 5] = x;
    __syncthreads();
    if (tid < 32) {
        int s = wsum[tid];
#pragma unroll
        for (int off = 1; off < 32; off <<= 1) {
            int t = __shfl_up_sync(0xffffffffu, s, off);
            if (tid >= off) s += t;
        }
        wsum[tid] = s;
    }
    __syncthreads();
    int incl = x + ((tid >= 32) ? wsum[(tid >> 5) - 1] : 0);
    if (i < n) g_rowptr[i] = incl - v;          // block-local exclusive
    if (tid == 1023) g_blocksums[blockIdx.x] = incl;
    if (i < n) g_dinv[i] = rsqrtf(g_deg[i]);    // deg >= 1 (self-loop)
}

// phase 2: each block reduces its prefix of block sums itself, adds offset
__global__ void k_scan_add(int n, int e) {
    __shared__ int s_off;
    int tid = threadIdx.x;
    if (tid < 32) {
        int bid = blockIdx.x;
        int v = 0;
        if (tid < bid) v = g_blocksums[tid];
        if (tid + 32 < bid) v += g_blocksums[tid + 32];
#pragma unroll
        for (int o = 16; o; o >>= 1) v += __shfl_down_sync(0xffffffffu, v, o);
        if (tid == 0) s_off = v;
    }
    __syncthreads();
    int i = blockIdx.x * 1024 + tid;
    if (i < n) {
        int r = g_rowptr[i] + s_off;
        g_rowptr[i] = r;
        g_cursor[i] = r;
    }
    if (i == 0) g_rowptr[n] = e;
}

__global__ void k_scatter(const int* __restrict__ src, const int* __restrict__ dst,
                          const float* __restrict__ ew, int e) {
    int i = blockIdx.x * blockDim.x + threadIdx.x;
    if (i < e) {
        int d = dst[i];
        int s = src[i];
        int pos = atomicAdd(&g_cursor[d], 1);
        g_srcs[pos]  = s;
        g_norms[pos] = g_dinv[s] * ew[i] * g_dinv[d];
    }
}

// ---------------------------------------------------------------------------
// mma / ldmatrix helpers
__device__ __forceinline__ void mma_f16(float* c, const unsigned* a, const unsigned* b) {
    asm volatile("mma.sync.aligned.m16n8k16.row.col.f32.f16.f16.f32 "
        "{%0,%1,%2,%3}, {%4,%5,%6,%7}, {%8,%9}, {%0,%1,%2,%3};"
        : "+f"(c[0]), "+f"(c[1]), "+f"(c[2]), "+f"(c[3])
        : "r"(a[0]), "r"(a[1]), "r"(a[2]), "r"(a[3]), "r"(b[0]), "r"(b[1]));
}

__device__ __forceinline__ void ldsm4(unsigned& r0, unsigned& r1, unsigned& r2, unsigned& r3,
                                      const void* p) {
    unsigned addr = (unsigned)__cvta_generic_to_shared(p);
    asm volatile("ldmatrix.sync.aligned.m8n8.x4.shared.b16 {%0,%1,%2,%3}, [%4];"
        : "=r"(r0), "=r"(r1), "=r"(r2), "=r"(r3) : "r"(addr));
}

__device__ __forceinline__ void ldsm4t(unsigned& r0, unsigned& r1, unsigned& r2, unsigned& r3,
                                       const void* p) {
    unsigned addr = (unsigned)__cvta_generic_to_shared(p);
    asm volatile("ldmatrix.sync.aligned.m8n8.x4.trans.shared.b16 {%0,%1,%2,%3}, [%4];"
        : "=r"(r0), "=r"(r1), "=r"(r2), "=r"(r3) : "r"(addr));
}

// ---------------------------------------------------------------------------
// Tensor-core GEMM (conv layers): C[M,128] = A[M,128] @ W[128,128]
// 2-term compensation: acc = Al*Bh + Ah*Bh; fp16 output for the aggregate.
template <int NC, bool OUT16>
__global__ void __launch_bounds__(256) k_gemm_tc(const float* __restrict__ A,
                                                 const float* __restrict__ W,
                                                 void* __restrict__ Cv, int M) {
    const int KC = 32, KP = 40;             // A rows padded: stride 80B, LDSM conflict-free
    const int NP = NC + 8;                  // B rows padded
    const int NF = NC / 16;
    const int NH = NC / 2;
    const int PB = (KC * NH) / 256;
    __shared__ __half As_h[128][KP], As_l[128][KP];
    __shared__ __half Bs_h[KC][NP];

    int tid  = threadIdx.x;
    int lane = tid & 31, wid = tid >> 5;
    int m0   = blockIdx.x * 128;
    int wm0  = (wid & 3) * 32;
    int wn0  = (wid >> 2) * (NC / 2);
    int gr = lane >> 2, gc = lane & 3;

    float acc[2][NF][4];
#pragma unroll
    for (int i = 0; i < 2; i++)
#pragma unroll
        for (int j = 0; j < NF; j++)
#pragma unroll
            for (int q = 0; q < 4; q++) acc[i][j][q] = 0.f;

    int r16 = tid >> 4;
    int c2  = tid & 15;

    float2 pa[8];
    float2 pb[PB];

    int atq = lane >> 3, arr = lane & 7;
    int am_off = (atq & 1) * 8 + arr;
    int ak_off = (atq >> 1) * 8;
    int bjj = lane >> 4, bt = (lane >> 3) & 1;
    int bk_off = bt * 8 + (lane & 7);

    auto loadA = [&](int k0) {
#pragma unroll
        for (int p = 0; p < 8; p++) {
            int gm = m0 + p * 16 + r16;
            pa[p] = (gm < M) ? *(const float2*)(A + (size_t)gm * 128 + k0 + 2 * c2)
                             : make_float2(0.f, 0.f);
        }
    };
    auto loadB = [&](int k0) {
#pragma unroll
        for (int p = 0; p < PB; p++) {
            int idx = p * 256 + tid;
            int kk = idx / NH, cb = idx % NH;
            pb[p] = *(const float2*)(W + (k0 + kk) * NC + 2 * cb);
        }
    };

    loadA(0);
    loadB(0);

#pragma unroll
    for (int k0 = 0; k0 < 128; k0 += KC) {
#pragma unroll
        for (int p = 0; p < 8; p++) {
            int r = p * 16 + r16;
            float2 v = pa[p];
            __half hx = __float2half_rn(v.x), hy = __float2half_rn(v.y);
            __half lx = __float2half_rn(v.x - __half2float(hx));
            __half ly = __float2half_rn(v.y - __half2float(hy));
            *(__half2*)&As_h[r][2 * c2] = __halves2half2(hx, hy);
            *(__half2*)&As_l[r][2 * c2] = __halves2half2(lx, ly);
        }
#pragma unroll
        for (int p = 0; p < PB; p++) {
            int idx = p * 256 + tid;
            int kk = idx / NH, cb = idx % NH;
            *(__half2*)&Bs_h[kk][2 * cb] = __floats2half2_rn(pb[p].x, pb[p].y);
        }
        __syncthreads();
        if (k0 + KC < 128) { loadA(k0 + KC); loadB(k0 + KC); }

#pragma unroll
        for (int k16 = 0; k16 < KC / 16; k16++) {
            int ks = k16 * 16;
            unsigned Ah[2][4], Al[2][4];
#pragma unroll
            for (int i = 0; i < 2; i++) {
                int am = wm0 + i * 16 + am_off;
                ldsm4(Ah[i][0], Ah[i][1], Ah[i][2], Ah[i][3], &As_h[am][ks + ak_off]);
                ldsm4(Al[i][0], Al[i][1], Al[i][2], Al[i][3], &As_l[am][ks + ak_off]);
            }
            unsigned Bh[NF][2];
#pragma unroll
            for (int jb = 0; jb < NF; jb += 2) {
                int bn = wn0 + (jb + bjj) * 8;
                int bk = ks + bk_off;
                ldsm4t(Bh[jb][0], Bh[jb][1], Bh[jb + 1][0], Bh[jb + 1][1], &Bs_h[bk][bn]);
            }
#pragma unroll
            for (int i = 0; i < 2; i++)
#pragma unroll
                for (int j = 0; j < NF; j++) {
                    mma_f16(acc[i][j], Al[i], Bh[j]);
                    mma_f16(acc[i][j], Ah[i], Bh[j]);
                }
        }
        __syncthreads();
    }

#pragma unroll
    for (int i = 0; i < 2; i++) {
#pragma unroll
        for (int j = 0; j < NF; j++) {
            int col = wn0 + j * 8 + gc * 2;
            int gm0 = m0 + wm0 + i * 16 + gr;
            if (OUT16) {
                __half* C = (__half*)Cv;
                if (gm0 < M)
                    *(__half2*)(C + (size_t)gm0 * NC + col) =
                        __floats2half2_rn(acc[i][j][0], acc[i][j][1]);
                if (gm0 + 8 < M)
                    *(__half2*)(C + (size_t)(gm0 + 8) * NC + col) =
                        __floats2half2_rn(acc[i][j][2], acc[i][j][3]);
            } else {
                float* C = (float*)Cv;
                if (gm0 < M)
                    *(float2*)(C + (size_t)gm0 * NC + col) = make_float2(acc[i][j][0], acc[i][j][1]);
                if (gm0 + 8 < M)
                    *(float2*)(C + (size_t)(gm0 + 8) * NC + col) = make_float2(acc[i][j][2], acc[i][j][3]);
            }
        }
    }
}

// ---------------------------------------------------------------------------
// Fused FC: out[M,64] = relu(A[M,128] @ Wf1 + bf1) @ Wf2 + bf2
#define SM_ASH 0
#define SM_ASL 10240
#define SM_BSH 20480          // 32 x 136 halves
#define SM_F   29184          // 128 x 136 halves (fc1 result, hi fp16)
#define SM_B2  64000          // 128 x 72 halves (Wf2)
#define SM_FUSED_TOTAL 82432

__global__ void __launch_bounds__(256) k_fc_fused(const float* __restrict__ A,
                                                  const float* __restrict__ W1,
                                                  const float* __restrict__ b1,
                                                  const float* __restrict__ W2,
                                                  const float* __restrict__ b2,
                                                  float* __restrict__ out, int M) {
    extern __shared__ char sm[];
    __half (*As_h)[40]  = (__half(*)[40])(sm + SM_ASH);
    __half (*As_l)[40]  = (__half(*)[40])(sm + SM_ASL);
    __half (*Bs_h)[136] = (__half(*)[136])(sm + SM_BSH);
    __half (*F)[136]    = (__half(*)[136])(sm + SM_F);
    __half (*B2)[72]    = (__half(*)[72])(sm + SM_B2);

    int tid  = threadIdx.x;
    int lane = tid & 31, wid = tid >> 5;
    int m0   = blockIdx.x * 128;
    int wm0  = (wid & 3) * 32;
    int wn0  = (wid >> 2) * 64;
    int gr = lane >> 2, gc = lane & 3;

    float acc[2][8][4];
#pragma unroll
    for (int i = 0; i < 2; i++)
#pragma unroll
        for (int j = 0; j < 8; j++)
#pragma unroll
            for (int q = 0; q < 4; q++) acc[i][j][q] = 0.f;

    int r16 = tid >> 4;
    int c2  = tid & 15;

    float2 pa[8];
    float2 pb[8];

    int atq = lane >> 3, arr = lane & 7;
    int am_off = (atq & 1) * 8 + arr;
    int ak_off = (atq >> 1) * 8;
    int bjj = lane >> 4, bt = (lane >> 3) & 1;
    int bk_off = bt * 8 + (lane & 7);

    auto loadA = [&](int k0) {
#pragma unroll
        for (int p = 0; p < 8; p++) {
            int gm = m0 + p * 16 + r16;
            pa[p] = (gm < M) ? *(const float2*)(A + (size_t)gm * 128 + k0 + 2 * c2)
                             : make_float2(0.f, 0.f);
        }
    };
    auto loadB = [&](int k0) {
#pragma unroll
        for (int p = 0; p < 8; p++) {
            int idx = p * 256 + tid;
            int kk = idx / 64, cb = idx % 64;
            pb[p] = *(const float2*)(W1 + (k0 + kk) * 128 + 2 * cb);
        }
    };

    loadA(0);
    loadB(0);

    // preload Wf2 [128,64] -> B2 (hi fp16, k-major); visible after next sync
#pragma unroll
    for (int p = 0; p < 32; p++) {
        int idx = p * 256 + tid;
        int kk = idx >> 6, nn = idx & 63;
        B2[kk][nn] = __float2half_rn(W2[idx]);
    }

    // ---- phase 1: fc1 (2-term) ----
#pragma unroll
    for (int k0 = 0; k0 < 128; k0 += 32) {
#pragma unroll
        for (int p = 0; p < 8; p++) {
            int r = p * 16 + r16;
            float2 v = pa[p];
            __half hx = __float2half_rn(v.x), hy = __float2half_rn(v.y);
            __half lx = __float2half_rn(v.x - __half2float(hx));
            __half ly = __float2half_rn(v.y - __half2float(hy));
            *(__half2*)&As_h[r][2 * c2] = __halves2half2(hx, hy);
            *(__half2*)&As_l[r][2 * c2] = __halves2half2(lx, ly);
        }
#pragma unroll
        for (int p = 0; p < 8; p++) {
            int idx = p * 256 + tid;
            int kk = idx / 64, cb = idx % 64;
            *(__half2*)&Bs_h[kk][2 * cb] = __floats2half2_rn(pb[p].x, pb[p].y);
        }
        __syncthreads();
        if (k0 + 32 < 128) { loadA(k0 + 32); loadB(k0 + 32); }

#pragma unroll
        for (int k16 = 0; k16 < 2; k16++) {
            int ks = k16 * 16;
            unsigned Ah[2][4], Al[2][4];
#pragma unroll
            for (int i = 0; i < 2; i++) {
                int am = wm0 + i * 16 + am_off;
                ldsm4(Ah[i][0], Ah[i][1], Ah[i][2], Ah[i][3], &As_h[am][ks + ak_off]);
                ldsm4(Al[i][0], Al[i][1], Al[i][2], Al[i][3], &As_l[am][ks + ak_off]);
            }
            unsigned Bh[8][2];
#pragma unroll
            for (int jb = 0; jb < 8; jb += 2) {
                int bn = wn0 + (jb + bjj) * 8;
                int bk = ks + bk_off;
                ldsm4t(Bh[jb][0], Bh[jb][1], Bh[jb + 1][0], Bh[jb + 1][1], &Bs_h[bk][bn]);
            }
#pragma unroll
            for (int i = 0; i < 2; i++)
#pragma unroll
                for (int j = 0; j < 8; j++) {
                    mma_f16(acc[i][j], Al[i], Bh[j]);
                    mma_f16(acc[i][j], Ah[i], Bh[j]);
                }
        }
        __syncthreads();
    }

    // epilogue 1: bias + relu -> F (fp16, smem), local rows
#pragma unroll
    for (int i = 0; i < 2; i++) {
#pragma unroll
        for (int j = 0; j < 8; j++) {
            int col = wn0 + j * 8 + gc * 2;
            float b0 = b1[col], bb1 = b1[col + 1];
            int r0 = wm0 + i * 16 + gr;
            float x0 = fmaxf(acc[i][j][0] + b0, 0.f), x1 = fmaxf(acc[i][j][1] + bb1, 0.f);
            float x2 = fmaxf(acc[i][j][2] + b0, 0.f), x3 = fmaxf(acc[i][j][3] + bb1, 0.f);
            *(__half2*)&F[r0][col]     = __floats2half2_rn(x0, x1);
            *(__half2*)&F[r0 + 8][col] = __floats2half2_rn(x2, x3);
        }
    }
    __syncthreads();

    // ---- phase 2: fc2 (N=64), A = F (hi fp16), B = B2; warp tile 32 cols ----
    int wn2 = (wid >> 2) * 32;
    float acc2[2][4][4];
#pragma unroll
    for (int i = 0; i < 2; i++)
#pragma unroll
        for (int j = 0; j < 4; j++)
#pragma unroll
            for (int q = 0; q < 4; q++) acc2[i][j][q] = 0.f;

#pragma unroll
    for (int k16 = 0; k16 < 8; k16++) {
        int ks = k16 * 16;
        unsigned Ah2[2][4];
#pragma unroll
        for (int i = 0; i < 2; i++) {
            int am = wm0 + i * 16 + am_off;
            ldsm4(Ah2[i][0], Ah2[i][1], Ah2[i][2], Ah2[i][3], &F[am][ks + ak_off]);
        }
        unsigned Bh2[4][2];
#pragma unroll
        for (int jb = 0; jb < 4; jb += 2) {
            int bn = wn2 + (jb + bjj) * 8;
            int bk = ks + bk_off;
            ldsm4t(Bh2[jb][0], Bh2[jb][1], Bh2[jb + 1][0], Bh2[jb + 1][1], &B2[bk][bn]);
        }
#pragma unroll
        for (int i = 0; i < 2; i++)
#pragma unroll
            for (int j = 0; j < 4; j++)
                mma_f16(acc2[i][j], Ah2[i], Bh2[j]);
    }

    // epilogue 2: bias -> fp32 out [M,64]
#pragma unroll
    for (int i = 0; i < 2; i++) {
#pragma unroll
        for (int j = 0; j < 4; j++) {
            int col = wn2 + j * 8 + gc * 2;
            float b0 = b2[col], bb1 = b2[col + 1];
            int gm0 = m0 + wm0 + i * 16 + gr;
            if (gm0 < M)
                *(float2*)(out + (size_t)gm0 * 64 + col) =
                    make_float2(acc2[i][j][0] + b0, acc2[i][j][1] + bb1);
            if (gm0 + 8 < M)
                *(float2*)(out + (size_t)(gm0 + 8) * 64 + col) =
                    make_float2(acc2[i][j][2] + b0, acc2[i][j][3] + bb1);
        }
    }
}

// ---------------------------------------------------------------------------
// out[i,:] = relu( sum_{p in CSR(i)} norm[p]*h16[src[p],:] + dinv[i]^2*h16[i,:] + bias )
__global__ void __launch_bounds__(256) k_aggregate(const __half* __restrict__ h,
                                                   const float* __restrict__ bias,
                                                   float* __restrict__ out, int n) {
    int warp = (blockIdx.x * blockDim.x + threadIdx.x) >> 5;
    int lane = threadIdx.x & 31;
    if (warp >= n) return;

    float di = g_dinv[warp];
    float sl = di * di;

    uint2 sv = ((const uint2*)(h + (size_t)warp * 128))[lane];
    float2 f0 = __half22float2(*(__half2*)&sv.x);
    float2 f1 = __half22float2(*(__half2*)&sv.y);
    float4 acc = make_float4(f0.x * sl, f0.y * sl, f1.x * sl, f1.y * sl);

    int p  = g_rowptr[warp];
    int p1 = g_rowptr[warp + 1];
    for (; p + 1 < p1; p += 2) {
        int   s0 = g_srcs[p],  s1 = g_srcs[p + 1];
        float w0 = g_norms[p], w1 = g_norms[p + 1];
        uint2 v0 = ((const uint2*)(h + (size_t)s0 * 128))[lane];
        uint2 v1 = ((const uint2*)(h + (size_t)s1 * 128))[lane];
        float2 a0 = __half22float2(*(__half2*)&v0.x);
        float2 a1 = __half22float2(*(__half2*)&v0.y);
        float2 b0 = __half22float2(*(__half2*)&v1.x);
        float2 b1 = __half22float2(*(__half2*)&v1.y);
        acc.x += w0 * a0.x + w1 * b0.x;
        acc.y += w0 * a0.y + w1 * b0.y;
        acc.z += w0 * a1.x + w1 * b1.x;
        acc.w += w0 * a1.y + w1 * b1.y;
    }
    if (p < p1) {
        int   s0 = g_srcs[p];
        float w0 = g_norms[p];
        uint2 v0 = ((const uint2*)(h + (size_t)s0 * 128))[lane];
        float2 a0 = __half22float2(*(__half2*)&v0.x);
        float2 a1 = __half22float2(*(__half2*)&v0.y);
        acc.x += w0 * a0.x;
        acc.y += w0 * a0.y;
        acc.z += w0 * a1.x;
        acc.w += w0 * a1.y;
    }
    float4 b = ((const float4*)bias)[lane];
    acc.x = fmaxf(acc.x + b.x, 0.f);
    acc.y = fmaxf(acc.y + b.y, 0.f);
    acc.z = fmaxf(acc.z + b.z, 0.f);
    acc.w = fmaxf(acc.w + b.w, 0.f);
    ((float4*)(out + (size_t)warp * 128))[lane] = acc;
}

// ---------------------------------------------------------------------------
extern "C" void kernel_launch(void* const* d_in, const int* in_sizes, int n_in,
                              void* d_out, int out_size) {
    const float* x   = (const float*)d_in[0];
    const int*   ei  = (const int*)  d_in[1];
    const float* ew  = (const float*)d_in[2];
    const float* W1  = (const float*)d_in[3];
    const float* b1  = (const float*)d_in[4];
    const float* W2  = (const float*)d_in[5];
    const float* b2  = (const float*)d_in[6];
    const float* Wf1 = (const float*)d_in[7];
    const float* bf1 = (const float*)d_in[8];
    const float* Wf2 = (const float*)d_in[9];
    const float* bf2 = (const float*)d_in[10];
    float* out = (float*)d_out;

    int n = in_sizes[0] / 128;   // 50000
    int e = in_sizes[2];         // 800000
    const int* src = ei;
    const int* dst = ei + e;

    float *bufA = nullptr, *bufB = nullptr;
    cudaGetSymbolAddress((void**)&bufA, g_bufA);
    cudaGetSymbolAddress((void**)&bufB, g_bufB);
    __half* bufA16 = (__half*)bufA;

    // one-time host-side resources (created on the uncaptured correctness call)
    static cudaStream_t s2 = nullptr;
    static cudaEvent_t evFork = nullptr, evJoin = nullptr;
    static int init_done = 0;
    if (!init_done) {
        cudaFuncSetAttribute(k_fc_fused, cudaFuncAttributeMaxDynamicSharedMemorySize,
                             SM_FUSED_TOTAL);
        cudaStreamCreateWithFlags(&s2, cudaStreamNonBlocking);
        cudaEventCreateWithFlags(&evFork, cudaEventDisableTiming);
        cudaEventCreateWithFlags(&evJoin, cudaEventDisableTiming);
        init_done = 1;
    }

    const int TB = 256;
    int gn = (n + TB - 1) / TB;
    int ge = (e + TB - 1) / TB;
    int nb = (n + 1023) / 1024;
    int gm = (n + 127) / 128;
    int ga = (n * 32 + TB - 1) / TB;   // one warp per node

    // fork: side stream builds the CSR while the main stream runs conv1 GEMM
    cudaEventRecord(evFork, 0);
    cudaStreamWaitEvent(s2, evFork, 0);

    // ---- side stream: graph preprocessing (degrees + CSR by dst)
    k_init<<<gn, TB, 0, s2>>>(n);
    k_edge_count<<<ge, TB, 0, s2>>>(src, dst, ew, e);
    k_scan_block<<<nb, 1024, 0, s2>>>(n);
    k_scan_add<<<nb, 1024, 0, s2>>>(n, e);
    k_scatter<<<ge, TB, 0, s2>>>(src, dst, ew, e);
    cudaEventRecord(evJoin, s2);

    // ---- main stream: conv1 GEMM (independent of CSR)
    k_gemm_tc<128, true><<<gm, TB>>>(x, W1, bufA16, n);

    // join: aggregate needs both conv1 output and the CSR
    cudaStreamWaitEvent(0, evJoin, 0);
    k_aggregate<<<ga, TB>>>(bufA16, b1, bufB, n);
    // conv2
    k_gemm_tc<128, true><<<gm, TB>>>(bufB, W2, bufA16, n);
    k_aggregate<<<ga, TB>>>(bufA16, b2, bufB, n);
    // fused fc1+fc2 -> fp32 output
    k_fc_fused<<<gm, TB, SM_FUSED_TOTAL>>>(bufB, Wf1, bf1, Wf2, bf2, out, n);
}

// round 17
// speedup vs baseline: 1.2158x; 1.0728x over previous
#include <cuda_runtime.h>
#include <cuda_fp16.h>

#define NMAX 50000
#define EMAX 800000

// ---- scratch (static device globals; allocation-free per harness rules) ----
__device__ float g_deg[NMAX];
__device__ float g_dinv[NMAX];
__device__ int   g_rowptr[NMAX + 1];
__device__ int   g_cursor[NMAX];
__device__ int   g_blocksums[64];
__device__ int   g_srcs[EMAX];
__device__ float g_norms[EMAX];
__device__ __align__(16) float g_bufA[(size_t)NMAX * 128];   // half storage (GEMM out)
__device__ __align__(16) float g_bufB[(size_t)NMAX * 128];   // half storage (agg out)

// ---------------------------------------------------------------------------
__global__ void k_init(int n) {
    int i = blockIdx.x * blockDim.x + threadIdx.x;
    if (i < n) { g_deg[i] = 1.0f; g_cursor[i] = 0; }  // self-loop weight 1
}

__global__ void k_edge_count(const int* __restrict__ src, const int* __restrict__ dst,
                             const float* __restrict__ ew, int e) {
    int i = blockIdx.x * blockDim.x + threadIdx.x;
    if (i < e) {
        int d = dst[i];
        atomicAdd(&g_deg[d], ew[i]);
        atomicAdd(&g_cursor[d], 1);
    }
}

// phase 1: per-block (1024) warp-shuffle scan of counts; fused dinv
__global__ void k_scan_block(int n) {
    __shared__ int wsum[32];
    int tid = threadIdx.x;
    int i = blockIdx.x * 1024 + tid;
    int v = (i < n) ? g_cursor[i] : 0;
    int x = v;
#pragma unroll
    for (int off = 1; off < 32; off <<= 1) {
        int t = __shfl_up_sync(0xffffffffu, x, off);
        if ((tid & 31) >= off) x += t;
    }
    if ((tid & 31) == 31) wsum[tid >> 5] = x;
    __syncthreads();
    if (tid < 32) {
        int s = wsum[tid];
#pragma unroll
        for (int off = 1; off < 32; off <<= 1) {
            int t = __shfl_up_sync(0xffffffffu, s, off);
            if (tid >= off) s += t;
        }
        wsum[tid] = s;
    }
    __syncthreads();
    int incl = x + ((tid >= 32) ? wsum[(tid >> 5) - 1] : 0);
    if (i < n) g_rowptr[i] = incl - v;          // block-local exclusive
    if (tid == 1023) g_blocksums[blockIdx.x] = incl;
    if (i < n) g_dinv[i] = rsqrtf(g_deg[i]);    // deg >= 1 (self-loop)
}

// phase 2: each block reduces its prefix of block sums itself, adds offset
__global__ void k_scan_add(int n, int e) {
    __shared__ int s_off;
    int tid = threadIdx.x;
    if (tid < 32) {
        int bid = blockIdx.x;
        int v = 0;
        if (tid < bid) v = g_blocksums[tid];
        if (tid + 32 < bid) v += g_blocksums[tid + 32];
#pragma unroll
        for (int o = 16; o; o >>= 1) v += __shfl_down_sync(0xffffffffu, v, o);
        if (tid == 0) s_off = v;
    }
    __syncthreads();
    int i = blockIdx.x * 1024 + tid;
    if (i < n) {
        int r = g_rowptr[i] + s_off;
        g_rowptr[i] = r;
        g_cursor[i] = r;
    }
    if (i == 0) g_rowptr[n] = e;
}

__global__ void k_scatter(const int* __restrict__ src, const int* __restrict__ dst,
                          const float* __restrict__ ew, int e) {
    int i = blockIdx.x * blockDim.x + threadIdx.x;
    if (i < e) {
        int d = dst[i];
        int s = src[i];
        int pos = atomicAdd(&g_cursor[d], 1);
        g_srcs[pos]  = s;
        g_norms[pos] = g_dinv[s] * ew[i] * g_dinv[d];
    }
}

// ---------------------------------------------------------------------------
// mma / ldmatrix helpers
__device__ __forceinline__ void mma_f16(float* c, const unsigned* a, const unsigned* b) {
    asm volatile("mma.sync.aligned.m16n8k16.row.col.f32.f16.f16.f32 "
        "{%0,%1,%2,%3}, {%4,%5,%6,%7}, {%8,%9}, {%0,%1,%2,%3};"
        : "+f"(c[0]), "+f"(c[1]), "+f"(c[2]), "+f"(c[3])
        : "r"(a[0]), "r"(a[1]), "r"(a[2]), "r"(a[3]), "r"(b[0]), "r"(b[1]));
}

__device__ __forceinline__ void ldsm4(unsigned& r0, unsigned& r1, unsigned& r2, unsigned& r3,
                                      const void* p) {
    unsigned addr = (unsigned)__cvta_generic_to_shared(p);
    asm volatile("ldmatrix.sync.aligned.m8n8.x4.shared.b16 {%0,%1,%2,%3}, [%4];"
        : "=r"(r0), "=r"(r1), "=r"(r2), "=r"(r3) : "r"(addr));
}

__device__ __forceinline__ void ldsm4t(unsigned& r0, unsigned& r1, unsigned& r2, unsigned& r3,
                                       const void* p) {
    unsigned addr = (unsigned)__cvta_generic_to_shared(p);
    asm volatile("ldmatrix.sync.aligned.m8n8.x4.trans.shared.b16 {%0,%1,%2,%3}, [%4];"
        : "=r"(r0), "=r"(r1), "=r"(r2), "=r"(r3) : "r"(addr));
}

// ---------------------------------------------------------------------------
// Tensor-core GEMM (conv layers): C[M,128] = A[M,128] @ W[128,128]
// A16=false: fp32 A, 2-term compensation (Al*Bh + Ah*Bh).
// A16=true:  fp16 A (already quantized), 1-term (Ah*Bh) — half the mma work.
template <int NC, bool A16, bool OUT16>
__global__ void __launch_bounds__(256) k_gemm_tc(const void* __restrict__ Av,
                                                 const float* __restrict__ W,
                                                 void* __restrict__ Cv, int M) {
    const int KC = 32, KP = 40;             // A rows padded: stride 80B, LDSM conflict-free
    const int NP = NC + 8;                  // B rows padded
    const int NF = NC / 16;
    const int NH = NC / 2;
    const int PB = (KC * NH) / 256;
    __shared__ __half As_h[128][KP];
    __shared__ __half As_l[A16 ? 1 : 128][KP];
    __shared__ __half Bs_h[KC][NP];

    int tid  = threadIdx.x;
    int lane = tid & 31, wid = tid >> 5;
    int m0   = blockIdx.x * 128;
    int wm0  = (wid & 3) * 32;
    int wn0  = (wid >> 2) * (NC / 2);
    int gr = lane >> 2, gc = lane & 3;

    float acc[2][NF][4];
#pragma unroll
    for (int i = 0; i < 2; i++)
#pragma unroll
        for (int j = 0; j < NF; j++)
#pragma unroll
            for (int q = 0; q < 4; q++) acc[i][j][q] = 0.f;

    int r16 = tid >> 4;
    int c2  = tid & 15;

    float2   pa[8];          // fp32 A prefetch
    unsigned pah[8];         // fp16 A prefetch
    float2   pb[PB];

    int atq = lane >> 3, arr = lane & 7;
    int am_off = (atq & 1) * 8 + arr;
    int ak_off = (atq >> 1) * 8;
    int bjj = lane >> 4, bt = (lane >> 3) & 1;
    int bk_off = bt * 8 + (lane & 7);

    auto loadA = [&](int k0) {
#pragma unroll
        for (int p = 0; p < 8; p++) {
            int gm = m0 + p * 16 + r16;
            if (A16) {
                pah[p] = (gm < M)
                    ? *(const unsigned*)((const __half*)Av + (size_t)gm * 128 + k0 + 2 * c2)
                    : 0u;
            } else {
                pa[p] = (gm < M)
                    ? *(const float2*)((const float*)Av + (size_t)gm * 128 + k0 + 2 * c2)
                    : make_float2(0.f, 0.f);
            }
        }
    };
    auto loadB = [&](int k0) {
#pragma unroll
        for (int p = 0; p < PB; p++) {
            int idx = p * 256 + tid;
            int kk = idx / NH, cb = idx % NH;
            pb[p] = *(const float2*)(W + (k0 + kk) * NC + 2 * cb);
        }
    };

    loadA(0);
    loadB(0);

#pragma unroll
    for (int k0 = 0; k0 < 128; k0 += KC) {
#pragma unroll
        for (int p = 0; p < 8; p++) {
            int r = p * 16 + r16;
            if (A16) {
                *(unsigned*)&As_h[r][2 * c2] = pah[p];
            } else {
                float2 v = pa[p];
                __half hx = __float2half_rn(v.x), hy = __float2half_rn(v.y);
                __half lx = __float2half_rn(v.x - __half2float(hx));
                __half ly = __float2half_rn(v.y - __half2float(hy));
                *(__half2*)&As_h[r][2 * c2] = __halves2half2(hx, hy);
                *(__half2*)&As_l[r][2 * c2] = __halves2half2(lx, ly);
            }
        }
#pragma unroll
        for (int p = 0; p < PB; p++) {
            int idx = p * 256 + tid;
            int kk = idx / NH, cb = idx % NH;
            *(__half2*)&Bs_h[kk][2 * cb] = __floats2half2_rn(pb[p].x, pb[p].y);
        }
        __syncthreads();
        if (k0 + KC < 128) { loadA(k0 + KC); loadB(k0 + KC); }

#pragma unroll
        for (int k16 = 0; k16 < KC / 16; k16++) {
            int ks = k16 * 16;
            unsigned Ah[2][4], Al[2][4];
#pragma unroll
            for (int i = 0; i < 2; i++) {
                int am = wm0 + i * 16 + am_off;
                ldsm4(Ah[i][0], Ah[i][1], Ah[i][2], Ah[i][3], &As_h[am][ks + ak_off]);
                if (!A16)
                    ldsm4(Al[i][0], Al[i][1], Al[i][2], Al[i][3], &As_l[am][ks + ak_off]);
            }
            unsigned Bh[NF][2];
#pragma unroll
            for (int jb = 0; jb < NF; jb += 2) {
                int bn = wn0 + (jb + bjj) * 8;
                int bk = ks + bk_off;
                ldsm4t(Bh[jb][0], Bh[jb][1], Bh[jb + 1][0], Bh[jb + 1][1], &Bs_h[bk][bn]);
            }
#pragma unroll
            for (int i = 0; i < 2; i++)
#pragma unroll
                for (int j = 0; j < NF; j++) {
                    if (!A16) mma_f16(acc[i][j], Al[i], Bh[j]);
                    mma_f16(acc[i][j], Ah[i], Bh[j]);
                }
        }
        __syncthreads();
    }

#pragma unroll
    for (int i = 0; i < 2; i++) {
#pragma unroll
        for (int j = 0; j < NF; j++) {
            int col = wn0 + j * 8 + gc * 2;
            int gm0 = m0 + wm0 + i * 16 + gr;
            if (OUT16) {
                __half* C = (__half*)Cv;
                if (gm0 < M)
                    *(__half2*)(C + (size_t)gm0 * NC + col) =
                        __floats2half2_rn(acc[i][j][0], acc[i][j][1]);
                if (gm0 + 8 < M)
                    *(__half2*)(C + (size_t)(gm0 + 8) * NC + col) =
                        __floats2half2_rn(acc[i][j][2], acc[i][j][3]);
            } else {
                float* C = (float*)Cv;
                if (gm0 < M)
                    *(float2*)(C + (size_t)gm0 * NC + col) = make_float2(acc[i][j][0], acc[i][j][1]);
                if (gm0 + 8 < M)
                    *(float2*)(C + (size_t)(gm0 + 8) * NC + col) = make_float2(acc[i][j][2], acc[i][j][3]);
            }
        }
    }
}

// ---------------------------------------------------------------------------
// Fused FC: out[M,64] = relu(A16[M,128] @ Wf1 + bf1) @ Wf2 + bf2
// Phase 1 = 1-term GEMM (A already fp16); F in smem; phase 2 = fc2 mma.
#define SM_ASH 0
#define SM_BSH 10240          // 32 x 136 halves
#define SM_F   18944          // 128 x 136 halves
#define SM_B2  53760          // 128 x 72 halves
#define SM_FUSED_TOTAL 72192

__global__ void __launch_bounds__(256) k_fc_fused(const __half* __restrict__ A,
                                                  const float* __restrict__ W1,
                                                  const float* __restrict__ b1,
                                                  const float* __restrict__ W2,
                                                  const float* __restrict__ b2,
                                                  float* __restrict__ out, int M) {
    extern __shared__ char sm[];
    __half (*As_h)[40]  = (__half(*)[40])(sm + SM_ASH);
    __half (*Bs_h)[136] = (__half(*)[136])(sm + SM_BSH);
    __half (*F)[136]    = (__half(*)[136])(sm + SM_F);
    __half (*B2)[72]    = (__half(*)[72])(sm + SM_B2);

    int tid  = threadIdx.x;
    int lane = tid & 31, wid = tid >> 5;
    int m0   = blockIdx.x * 128;
    int wm0  = (wid & 3) * 32;
    int wn0  = (wid >> 2) * 64;
    int gr = lane >> 2, gc = lane & 3;

    float acc[2][8][4];
#pragma unroll
    for (int i = 0; i < 2; i++)
#pragma unroll
        for (int j = 0; j < 8; j++)
#pragma unroll
            for (int q = 0; q < 4; q++) acc[i][j][q] = 0.f;

    int r16 = tid >> 4;
    int c2  = tid & 15;

    unsigned pah[8];
    float2 pb[8];

    int atq = lane >> 3, arr = lane & 7;
    int am_off = (atq & 1) * 8 + arr;
    int ak_off = (atq >> 1) * 8;
    int bjj = lane >> 4, bt = (lane >> 3) & 1;
    int bk_off = bt * 8 + (lane & 7);

    auto loadA = [&](int k0) {
#pragma unroll
        for (int p = 0; p < 8; p++) {
            int gm = m0 + p * 16 + r16;
            pah[p] = (gm < M)
                ? *(const unsigned*)(A + (size_t)gm * 128 + k0 + 2 * c2) : 0u;
        }
    };
    auto loadB = [&](int k0) {
#pragma unroll
        for (int p = 0; p < 8; p++) {
            int idx = p * 256 + tid;
            int kk = idx / 64, cb = idx % 64;
            pb[p] = *(const float2*)(W1 + (k0 + kk) * 128 + 2 * cb);
        }
    };

    loadA(0);
    loadB(0);

    // preload Wf2 [128,64] -> B2 (hi fp16, k-major); visible after next sync
#pragma unroll
    for (int p = 0; p < 32; p++) {
        int idx = p * 256 + tid;
        int kk = idx >> 6, nn = idx & 63;
        B2[kk][nn] = __float2half_rn(W2[idx]);
    }

    // ---- phase 1: fc1 (1-term, A fp16) ----
#pragma unroll
    for (int k0 = 0; k0 < 128; k0 += 32) {
#pragma unroll
        for (int p = 0; p < 8; p++) {
            int r = p * 16 + r16;
            *(unsigned*)&As_h[r][2 * c2] = pah[p];
        }
#pragma unroll
        for (int p = 0; p < 8; p++) {
            int idx = p * 256 + tid;
            int kk = idx / 64, cb = idx % 64;
            *(__half2*)&Bs_h[kk][2 * cb] = __floats2half2_rn(pb[p].x, pb[p].y);
        }
        __syncthreads();
        if (k0 + 32 < 128) { loadA(k0 + 32); loadB(k0 + 32); }

#pragma unroll
        for (int k16 = 0; k16 < 2; k16++) {
            int ks = k16 * 16;
            unsigned Ah[2][4];
#pragma unroll
            for (int i = 0; i < 2; i++) {
                int am = wm0 + i * 16 + am_off;
                ldsm4(Ah[i][0], Ah[i][1], Ah[i][2], Ah[i][3], &As_h[am][ks + ak_off]);
            }
            unsigned Bh[8][2];
#pragma unroll
            for (int jb = 0; jb < 8; jb += 2) {
                int bn = wn0 + (jb + bjj) * 8;
                int bk = ks + bk_off;
                ldsm4t(Bh[jb][0], Bh[jb][1], Bh[jb + 1][0], Bh[jb + 1][1], &Bs_h[bk][bn]);
            }
#pragma unroll
            for (int i = 0; i < 2; i++)
#pragma unroll
                for (int j = 0; j < 8; j++)
                    mma_f16(acc[i][j], Ah[i], Bh[j]);
        }
        __syncthreads();
    }

    // epilogue 1: bias + relu -> F (fp16, smem), local rows
#pragma unroll
    for (int i = 0; i < 2; i++) {
#pragma unroll
        for (int j = 0; j < 8; j++) {
            int col = wn0 + j * 8 + gc * 2;
            float b0 = b1[col], bb1 = b1[col + 1];
            int r0 = wm0 + i * 16 + gr;
            float x0 = fmaxf(acc[i][j][0] + b0, 0.f), x1 = fmaxf(acc[i][j][1] + bb1, 0.f);
            float x2 = fmaxf(acc[i][j][2] + b0, 0.f), x3 = fmaxf(acc[i][j][3] + bb1, 0.f);
            *(__half2*)&F[r0][col]     = __floats2half2_rn(x0, x1);
            *(__half2*)&F[r0 + 8][col] = __floats2half2_rn(x2, x3);
        }
    }
    __syncthreads();

    // ---- phase 2: fc2 (N=64), A = F, B = B2; warp tile 32 cols ----
    int wn2 = (wid >> 2) * 32;
    float acc2[2][4][4];
#pragma unroll
    for (int i = 0; i < 2; i++)
#pragma unroll
        for (int j = 0; j < 4; j++)
#pragma unroll
            for (int q = 0; q < 4; q++) acc2[i][j][q] = 0.f;

#pragma unroll
    for (int k16 = 0; k16 < 8; k16++) {
        int ks = k16 * 16;
        unsigned Ah2[2][4];
#pragma unroll
        for (int i = 0; i < 2; i++) {
            int am = wm0 + i * 16 + am_off;
            ldsm4(Ah2[i][0], Ah2[i][1], Ah2[i][2], Ah2[i][3], &F[am][ks + ak_off]);
        }
        unsigned Bh2[4][2];
#pragma unroll
        for (int jb = 0; jb < 4; jb += 2) {
            int bn = wn2 + (jb + bjj) * 8;
            int bk = ks + bk_off;
            ldsm4t(Bh2[jb][0], Bh2[jb][1], Bh2[jb + 1][0], Bh2[jb + 1][1], &B2[bk][bn]);
        }
#pragma unroll
        for (int i = 0; i < 2; i++)
#pragma unroll
            for (int j = 0; j < 4; j++)
                mma_f16(acc2[i][j], Ah2[i], Bh2[j]);
    }

    // epilogue 2: bias -> fp32 out [M,64]
#pragma unroll
    for (int i = 0; i < 2; i++) {
#pragma unroll
        for (int j = 0; j < 4; j++) {
            int col = wn2 + j * 8 + gc * 2;
            float b0 = b2[col], bb1 = b2[col + 1];
            int gm0 = m0 + wm0 + i * 16 + gr;
            if (gm0 < M)
                *(float2*)(out + (size_t)gm0 * 64 + col) =
                    make_float2(acc2[i][j][0] + b0, acc2[i][j][1] + bb1);
            if (gm0 + 8 < M)
                *(float2*)(out + (size_t)(gm0 + 8) * 64 + col) =
                    make_float2(acc2[i][j][2] + b0, acc2[i][j][3] + bb1);
        }
    }
}

// ---------------------------------------------------------------------------
// out16[i,:] = fp16( relu( sum norm*h16[src] + dinv^2*h16[i] + bias ) )
// fp32 accumulation; one warp per node, 4 dims/lane; fp16 output (half stores).
__global__ void __launch_bounds__(256) k_aggregate(const __half* __restrict__ h,
                                                   const float* __restrict__ bias,
                                                   __half* __restrict__ out, int n) {
    int warp = (blockIdx.x * blockDim.x + threadIdx.x) >> 5;
    int lane = threadIdx.x & 31;
    if (warp >= n) return;

    float di = g_dinv[warp];
    float sl = di * di;

    uint2 sv = ((const uint2*)(h + (size_t)warp * 128))[lane];
    float2 f0 = __half22float2(*(__half2*)&sv.x);
    float2 f1 = __half22float2(*(__half2*)&sv.y);
    float4 acc = make_float4(f0.x * sl, f0.y * sl, f1.x * sl, f1.y * sl);

    int p  = g_rowptr[warp];
    int p1 = g_rowptr[warp + 1];
    for (; p + 1 < p1; p += 2) {
        int   s0 = g_srcs[p],  s1 = g_srcs[p + 1];
        float w0 = g_norms[p], w1 = g_norms[p + 1];
        uint2 v0 = ((const uint2*)(h + (size_t)s0 * 128))[lane];
        uint2 v1 = ((const uint2*)(h + (size_t)s1 * 128))[lane];
        float2 a0 = __half22float2(*(__half2*)&v0.x);
        float2 a1 = __half22float2(*(__half2*)&v0.y);
        float2 b0 = __half22float2(*(__half2*)&v1.x);
        float2 b1 = __half22float2(*(__half2*)&v1.y);
        acc.x += w0 * a0.x + w1 * b0.x;
        acc.y += w0 * a0.y + w1 * b0.y;
        acc.z += w0 * a1.x + w1 * b1.x;
        acc.w += w0 * a1.y + w1 * b1.y;
    }
    if (p < p1) {
        int   s0 = g_srcs[p];
        float w0 = g_norms[p];
        uint2 v0 = ((const uint2*)(h + (size_t)s0 * 128))[lane];
        float2 a0 = __half22float2(*(__half2*)&v0.x);
        float2 a1 = __half22float2(*(__half2*)&v0.y);
        acc.x += w0 * a0.x;
        acc.y += w0 * a0.y;
        acc.z += w0 * a1.x;
        acc.w += w0 * a1.y;
    }
    float4 b = ((const float4*)bias)[lane];
    acc.x = fmaxf(acc.x + b.x, 0.f);
    acc.y = fmaxf(acc.y + b.y, 0.f);
    acc.z = fmaxf(acc.z + b.z, 0.f);
    acc.w = fmaxf(acc.w + b.w, 0.f);

    __half2 h0 = __floats2half2_rn(acc.x, acc.y);
    __half2 h1 = __floats2half2_rn(acc.z, acc.w);
    uint2 o;
    o.x = *(unsigned*)&h0; o.y = *(unsigned*)&h1;
    ((uint2*)(out + (size_t)warp * 128))[lane] = o;
}

// ---------------------------------------------------------------------------
extern "C" void kernel_launch(void* const* d_in, const int* in_sizes, int n_in,
                              void* d_out, int out_size) {
    const float* x   = (const float*)d_in[0];
    const int*   ei  = (const int*)  d_in[1];
    const float* ew  = (const float*)d_in[2];
    const float* W1  = (const float*)d_in[3];
    const float* b1  = (const float*)d_in[4];
    const float* W2  = (const float*)d_in[5];
    const float* b2  = (const float*)d_in[6];
    const float* Wf1 = (const float*)d_in[7];
    const float* bf1 = (const float*)d_in[8];
    const float* Wf2 = (const float*)d_in[9];
    const float* bf2 = (const float*)d_in[10];
    float* out = (float*)d_out;

    int n = in_sizes[0] / 128;   // 50000
    int e = in_sizes[2];         // 800000
    const int* src = ei;
    const int* dst = ei + e;

    float *bufA = nullptr, *bufB = nullptr;
    cudaGetSymbolAddress((void**)&bufA, g_bufA);
    cudaGetSymbolAddress((void**)&bufB, g_bufB);
    __half* bufA16 = (__half*)bufA;
    __half* bufB16 = (__half*)bufB;

    // one-time host-side resources (created on the uncaptured correctness call)
    static cudaStream_t s2 = nullptr;
    static cudaEvent_t evFork = nullptr, evJoin = nullptr;
    static int init_done = 0;
    if (!init_done) {
        cudaFuncSetAttribute(k_fc_fused, cudaFuncAttributeMaxDynamicSharedMemorySize,
                             SM_FUSED_TOTAL);
        cudaStreamCreateWithFlags(&s2, cudaStreamNonBlocking);
        cudaEventCreateWithFlags(&evFork, cudaEventDisableTiming);
        cudaEventCreateWithFlags(&evJoin, cudaEventDisableTiming);
        init_done = 1;
    }

    const int TB = 256;
    int gn = (n + TB - 1) / TB;
    int ge = (e + TB - 1) / TB;
    int nb = (n + 1023) / 1024;
    int gm = (n + 127) / 128;
    int ga = (n * 32 + TB - 1) / TB;   // one warp per node

    // fork: side stream builds the CSR while the main stream runs conv1 GEMM
    cudaEventRecord(evFork, 0);
    cudaStreamWaitEvent(s2, evFork, 0);

    // ---- side stream: graph preprocessing (degrees + CSR by dst)
    k_init<<<gn, TB, 0, s2>>>(n);
    k_edge_count<<<ge, TB, 0, s2>>>(src, dst, ew, e);
    k_scan_block<<<nb, 1024, 0, s2>>>(n);
    k_scan_add<<<nb, 1024, 0, s2>>>(n, e);
    k_scatter<<<ge, TB, 0, s2>>>(src, dst, ew, e);
    cudaEventRecord(evJoin, s2);

    // ---- main stream: conv1 GEMM (fp32 A, 2-term)
    k_gemm_tc<128, false, true><<<gm, TB>>>(x, W1, bufA16, n);

    // join: aggregate needs both conv1 output and the CSR
    cudaStreamWaitEvent(0, evJoin, 0);
    k_aggregate<<<ga, TB>>>(bufA16, b1, bufB16, n);
    // conv2: fp16 A, 1-term
    k_gemm_tc<128, true, true><<<gm, TB>>>(bufB16, W2, bufA16, n);
    k_aggregate<<<ga, TB>>>(bufA16, b2, bufB16, n);
    // fused fc1+fc2 (fp16 A, 1-term phase 1) -> fp32 output
    k_fc_fused<<<gm, TB, SM_FUSED_TOTAL>>>(bufB16, Wf1, bf1, Wf2, bf2, out, n);
}